// round 1
// baseline (speedup 1.0000x reference)
#include <cuda_runtime.h>

#define BB 32
#define LL 1024
#define CC 512
#define MT (BB*CC)     // 16384 rows (b,c)
#define KM 64          // modes
#define NF 128         // 2*KM (real | imag)
#define PADW 12
#define KERN 25

// -------- scratch (static device allocations; no cudaMalloc) --------
__device__ float g_res[MT*LL];        // residual, [m=(b,c)][l]
__device__ float g_trend[MT*LL];      // trend,    [m][l]
__device__ float g_trendout[MT*LL];   // general-path trend GEMM out [m][p]
__device__ float g_a[MT*NF];          // DFT coeffs [m][0:64 real | 64:128 imag]
__device__ float g_o[MT*NF];          // mixed coeffs, same layout
__device__ float g_d[MT];             // fast-path trend dot per (b,c)
__device__ float g_basisF[LL*NF];     // forward DFT basis [l][n]
__device__ float g_basisI[NF*LL];     // inverse DFT basis [kk][l]
__device__ int   g_same;              // 1 if all W_trend rows identical

// -------------------------------------------------------------------
__global__ void k_init() { g_same = 1; }

__global__ void k_check(const float* __restrict__ W) {
    int p = blockIdx.x;
    if (p == 0) return;
    int l = threadIdx.x * 4;
    float4 a = *(const float4*)(W + (size_t)p*LL + l);
    float4 b = *(const float4*)(W + l);
    if (a.x != b.x || a.y != b.y || a.z != b.z || a.w != b.w) g_same = 0;
}

// build forward + inverse DFT bases; exact integer phase reduction
__global__ void k_basis() {
    int i = blockIdx.x * 256 + threadIdx.x;   // 131072 total
    const float w0 = 6.2831853071795864769f / 1024.0f;
    {   // forward: basisF[l][n], n<64: cos(2pi k l/L), n>=64: -sin
        int l = i >> 7, n = i & 127, k = n & 63;
        int r = (k * l) & 1023;
        float s, c;
        sincosf(w0 * (float)r, &s, &c);
        g_basisF[i] = (n < KM) ? c : -s;
    }
    {   // inverse: basisI[kk][l]
        int kk = i >> 10, l = i & 1023, k = kk & 63;
        int r = (k * l) & 1023;
        float s, c;
        sincosf(w0 * (float)r, &s, &c);
        float v;
        if (kk < KM) v = (k == 0 ? 1.0f : 2.0f * c) * (1.0f / 1024.0f);
        else         v = (k == 0 ? 0.0f : -2.0f * s) * (1.0f / 1024.0f);
        g_basisI[i] = v;
    }
}

// -------- series_decomp: moving avg (edge-replicated) + transpose to [m][l]
__global__ void __launch_bounds__(256) k_decomp(const float* __restrict__ x) {
    __shared__ float xs[56][65];
    int c0 = blockIdx.x * 64;
    int l0 = blockIdx.y * 32;
    int b  = blockIdx.z;
    int tid = threadIdx.x;
    #pragma unroll
    for (int r = 0; r < 14; r++) {
        int idx = tid + r * 256;
        int lz = idx >> 6, cc = idx & 63;
        int lg = l0 - PADW + lz;
        lg = lg < 0 ? 0 : (lg > LL - 1 ? LL - 1 : lg);
        xs[lz][cc] = x[((size_t)b * LL + lg) * CC + c0 + cc];
    }
    __syncthreads();
    int cc = tid >> 2;
    int lq = tid & 3;
    int lbase = lq * 8;
    float s = 0.f;
    #pragma unroll
    for (int t = 0; t < KERN; t++) s += xs[lbase + t][cc];
    float trv[8], rsv[8];
    #pragma unroll
    for (int j = 0; j < 8; j++) {
        float tv = s * (1.0f / KERN);
        trv[j] = tv;
        rsv[j] = xs[lbase + j + PADW][cc] - tv;
        if (j < 7) s += xs[lbase + j + KERN][cc] - xs[lbase + j][cc];
    }
    size_t m = (size_t)b * CC + c0 + cc;
    float* td = &g_trend[m * LL + l0 + lbase];
    float* rd = &g_res  [m * LL + l0 + lbase];
    *(float4*)td       = make_float4(trv[0], trv[1], trv[2], trv[3]);
    *(float4*)(td + 4) = make_float4(trv[4], trv[5], trv[6], trv[7]);
    *(float4*)rd       = make_float4(rsv[0], rsv[1], rsv[2], rsv[3]);
    *(float4*)(rd + 4) = make_float4(rsv[4], rsv[5], rsv[6], rsv[7]);
}

// -------- fast-path trend: d[m] = dot(W row0, trend[m,:])
__global__ void __launch_bounds__(256) k_dot(const float* __restrict__ W) {
    if (!g_same) return;
    int warp = threadIdx.x >> 5, lane = threadIdx.x & 31;
    int row = blockIdx.x * 8 + warp;
    const float* tr = &g_trend[(size_t)row * LL];
    float s = 0.f;
    #pragma unroll 8
    for (int j = lane; j < LL; j += 32) s += W[j] * tr[j];
    #pragma unroll
    for (int off = 16; off; off >>= 1) s += __shfl_down_sync(0xffffffffu, s, off);
    if (lane == 0) g_d[row] = s;
}

// -------- general-path trend GEMM fallback (only if W rows differ)
__global__ void __launch_bounds__(256) k_trend_gemm(const float* __restrict__ W) {
    if (g_same) return;
    __shared__ float As[16][68];
    __shared__ float Bs[16][68];
    int m0 = blockIdx.x * 64;
    int p0 = blockIdx.y * 64;
    int tid = threadIdx.x;
    int mg = tid >> 4, pg = tid & 15;
    float acc[4][4] = {};
    for (int k0 = 0; k0 < LL; k0 += 16) {
        int rr = tid >> 2, kq = (tid & 3) * 4;
        float4 va = *(const float4*)&g_trend[(size_t)(m0 + rr) * LL + k0 + kq];
        As[kq][rr] = va.x; As[kq+1][rr] = va.y; As[kq+2][rr] = va.z; As[kq+3][rr] = va.w;
        float4 vb = *(const float4*)&W[(size_t)(p0 + rr) * LL + k0 + kq];
        Bs[kq][rr] = vb.x; Bs[kq+1][rr] = vb.y; Bs[kq+2][rr] = vb.z; Bs[kq+3][rr] = vb.w;
        __syncthreads();
        #pragma unroll
        for (int kk = 0; kk < 16; kk++)
            #pragma unroll
            for (int i = 0; i < 4; i++) {
                float av = As[kk][mg * 4 + i];
                #pragma unroll
                for (int j = 0; j < 4; j++)
                    acc[i][j] += av * Bs[kk][pg * 4 + j];
            }
        __syncthreads();
    }
    #pragma unroll
    for (int i = 0; i < 4; i++) {
        float* dst = &g_trendout[(size_t)(m0 + mg * 4 + i) * LL + p0 + pg * 4];
        *(float4*)dst = make_float4(acc[i][0], acc[i][1], acc[i][2], acc[i][3]);
    }
}

// -------- GEMM1: forward DFT  a[m][n] = sum_l res[m][l] * basisF[l][n]
__global__ void __launch_bounds__(256) k_gemm1() {
    __shared__ float As[16][64];   // [k][m]
    __shared__ float Bs[16][128];  // [k][n]
    int m0 = blockIdx.x * 64;
    int tid = threadIdx.x;
    int tr = tid >> 4;   // m group (4 m each)
    int tc = tid & 15;   // n group (8 n each) -> n fast for coalesced stores
    float acc[4][8] = {};
    for (int k0 = 0; k0 < LL; k0 += 16) {
        {
            int mm = tid >> 2, kq = (tid & 3) * 4;
            float4 v = *(const float4*)&g_res[(size_t)(m0 + mm) * LL + k0 + kq];
            As[kq][mm] = v.x; As[kq+1][mm] = v.y; As[kq+2][mm] = v.z; As[kq+3][mm] = v.w;
        }
        #pragma unroll
        for (int r = 0; r < 2; r++) {
            int f4 = tid + r * 256;
            int row = f4 >> 5;
            int c4 = (f4 & 31) * 4;
            *(float4*)&Bs[row][c4] = *(const float4*)&g_basisF[(k0 + row) * NF + c4];
        }
        __syncthreads();
        #pragma unroll
        for (int kk = 0; kk < 16; kk++) {
            float a[4], bv[8];
            float4 va = *(float4*)&As[kk][tr * 4];
            a[0] = va.x; a[1] = va.y; a[2] = va.z; a[3] = va.w;
            float4 b0 = *(float4*)&Bs[kk][tc * 8];
            float4 b1 = *(float4*)&Bs[kk][tc * 8 + 4];
            bv[0]=b0.x; bv[1]=b0.y; bv[2]=b0.z; bv[3]=b0.w;
            bv[4]=b1.x; bv[5]=b1.y; bv[6]=b1.z; bv[7]=b1.w;
            #pragma unroll
            for (int i = 0; i < 4; i++)
                #pragma unroll
                for (int j = 0; j < 8; j++)
                    acc[i][j] += a[i] * bv[j];
        }
        __syncthreads();
    }
    #pragma unroll
    for (int i = 0; i < 4; i++) {
        float* dst = &g_a[(size_t)(m0 + tr * 4 + i) * NF + tc * 8];
        *(float4*)dst       = make_float4(acc[i][0], acc[i][1], acc[i][2], acc[i][3]);
        *(float4*)(dst + 4) = make_float4(acc[i][4], acc[i][5], acc[i][6], acc[i][7]);
    }
}

// -------- GEMM2: per-mode mixing  o_{r/i}[b,o,k] = sum_i a_{r/i}[b,i,k] * w_{r/i}[i,o,k]
__global__ void __launch_bounds__(256) k_gemm2(const float* __restrict__ wr,
                                               const float* __restrict__ wi) {
    __shared__ float sa[4][8][128];  // [ii][b][kk]
    int o0 = blockIdx.x * 16;
    int b0 = blockIdx.y * 8;
    int tid = threadIdx.x;
    int k  = tid & 63;
    int oq = tid >> 6;  // 0..3, each owns 4 output channels
    float accr[8][4] = {};
    float acci[8][4] = {};
    for (int i0 = 0; i0 < CC; i0 += 4) {
        __syncthreads();
        #pragma unroll
        for (int r = 0; r < 4; r++) {
            int f4 = tid + r * 256;          // 1024 float4 total
            int row = f4 >> 5;               // 0..31
            int c4 = (f4 & 31) * 4;
            int ii = row >> 3, bb = row & 7;
            *(float4*)&sa[ii][bb][c4] =
                *(const float4*)&g_a[(size_t)((b0 + bb) * CC + i0 + ii) * NF + c4];
        }
        __syncthreads();
        #pragma unroll
        for (int ii = 0; ii < 4; ii++) {
            int i = i0 + ii;
            float w_r[4], w_i[4];
            #pragma unroll
            for (int j = 0; j < 4; j++) {
                int o = o0 + oq * 4 + j;
                size_t widx = ((size_t)i * CC + o) * KM + k;
                w_r[j] = wr[widx];
                w_i[j] = wi[widx];
            }
            #pragma unroll
            for (int bb = 0; bb < 8; bb++) {
                float ar = sa[ii][bb][k];
                float ai = sa[ii][bb][64 + k];
                #pragma unroll
                for (int j = 0; j < 4; j++) {
                    accr[bb][j] += ar * w_r[j];
                    acci[bb][j] += ai * w_i[j];
                }
            }
        }
    }
    #pragma unroll
    for (int bb = 0; bb < 8; bb++)
        #pragma unroll
        for (int j = 0; j < 4; j++) {
            int o = o0 + oq * 4 + j;
            size_t row = (size_t)(b0 + bb) * CC + o;
            g_o[row * NF + k]      = accr[bb][j];
            g_o[row * NF + 64 + k] = acci[bb][j];
        }
}

// -------- GEMM3: inverse DFT + trend + bias + transpose to [b][l][c]
__global__ void __launch_bounds__(256) k_gemm3(const float* __restrict__ btr,
                                               float* __restrict__ out) {
    __shared__ float As[16][128];  // [kk][m]
    __shared__ float Bs[16][64];   // [kk][l]
    int m0 = blockIdx.x * 128;
    int l0 = blockIdx.y * 64;
    int tid = threadIdx.x;
    int tr = tid & 15;   // m fast (c contiguous on store)
    int tc = tid >> 4;   // l slow
    float acc[4][8] = {};  // [nj][mi]
    for (int k0 = 0; k0 < NF; k0 += 16) {
        #pragma unroll
        for (int r = 0; r < 2; r++) {
            int id = tid + r * 256;
            int mm = id >> 2;
            int kq = (id & 3) * 4;
            float4 v = *(const float4*)&g_o[(size_t)(m0 + mm) * NF + k0 + kq];
            As[kq][mm] = v.x; As[kq+1][mm] = v.y; As[kq+2][mm] = v.z; As[kq+3][mm] = v.w;
        }
        {
            int row = tid >> 4;
            int c4 = (tid & 15) * 4;
            *(float4*)&Bs[row][c4] = *(const float4*)&g_basisI[(k0 + row) * LL + l0 + c4];
        }
        __syncthreads();
        #pragma unroll
        for (int kk = 0; kk < 16; kk++) {
            float a[8], bv[4];
            float4 a0 = *(float4*)&As[kk][tr * 8];
            float4 a1 = *(float4*)&As[kk][tr * 8 + 4];
            a[0]=a0.x; a[1]=a0.y; a[2]=a0.z; a[3]=a0.w;
            a[4]=a1.x; a[5]=a1.y; a[6]=a1.z; a[7]=a1.w;
            float4 vb = *(float4*)&Bs[kk][tc * 4];
            bv[0]=vb.x; bv[1]=vb.y; bv[2]=vb.z; bv[3]=vb.w;
            #pragma unroll
            for (int j = 0; j < 4; j++)
                #pragma unroll
                for (int i = 0; i < 8; i++)
                    acc[j][i] += a[i] * bv[j];
        }
        __syncthreads();
    }
    int m_base = m0 + tr * 8;
    int bidx = m_base >> 9;
    int c = m_base & 511;
    bool same = (g_same != 0);
    float dm[8];
    #pragma unroll
    for (int i = 0; i < 8; i++) dm[i] = same ? g_d[m_base + i] : 0.f;
    #pragma unroll
    for (int j = 0; j < 4; j++) {
        int l = l0 + tc * 4 + j;
        float bias = btr[l];
        float vals[8];
        #pragma unroll
        for (int i = 0; i < 8; i++) {
            float t = same ? dm[i] : g_trendout[(size_t)(m_base + i) * LL + l];
            vals[i] = acc[j][i] + bias + t;
        }
        float* dst = &out[((size_t)bidx * LL + l) * CC + c];
        *(float4*)dst       = make_float4(vals[0], vals[1], vals[2], vals[3]);
        *(float4*)(dst + 4) = make_float4(vals[4], vals[5], vals[6], vals[7]);
    }
}

// -------------------------------------------------------------------
extern "C" void kernel_launch(void* const* d_in, const int* in_sizes, int n_in,
                              void* d_out, int out_size) {
    const float* x  = (const float*)d_in[0];
    const float* W  = (const float*)d_in[1];
    const float* bt = (const float*)d_in[2];
    const float* wr = (const float*)d_in[3];
    const float* wi = (const float*)d_in[4];
    float* out = (float*)d_out;

    k_init<<<1, 1>>>();
    k_check<<<1024, 256>>>(W);
    k_basis<<<512, 256>>>();
    k_decomp<<<dim3(8, 32, 32), 256>>>(x);
    k_dot<<<2048, 256>>>(W);
    k_trend_gemm<<<dim3(256, 16), 256>>>(W);   // no-op on fast path
    k_gemm1<<<256, 256>>>();
    k_gemm2<<<dim3(32, 4), 256>>>(wr, wi);
    k_gemm3<<<dim3(128, 16), 256>>>(bt, out);
}